// round 15
// baseline (speedup 1.0000x reference)
#include <cuda_runtime.h>
#include <cuda_fp16.h>
#include <math.h>
#include <cstdint>

// Problem constants
constexpr int cB = 2, cT = 2048, cS = 2048, cD = 1024, cH = 16, cDK = 64;
constexpr int cHD = cH * cDK;      // 1024
constexpr int cMT = cB * cT;       // 4096
constexpr size_t XSZ = (size_t)cMT * cD;
constexpr size_t WSZ = (size_t)cD * cHD;

using f16 = __half;

// ---- helpers ----
__device__ __forceinline__ uint32_t smem_u32(const void* p) {
    uint32_t a;
    asm("{ .reg .u64 t; cvta.to.shared.u64 t, %1; cvt.u32.u64 %0, t; }"
        : "=r"(a) : "l"(p));
    return a;
}
__device__ __forceinline__ void ldsm4(uint32_t& r0, uint32_t& r1,
                                      uint32_t& r2, uint32_t& r3, uint32_t a) {
    asm volatile("ldmatrix.sync.aligned.m8n8.x4.shared.b16 {%0,%1,%2,%3}, [%4];"
                 : "=r"(r0), "=r"(r1), "=r"(r2), "=r"(r3) : "r"(a));
}
__device__ __forceinline__ void ldsm4t(uint32_t& r0, uint32_t& r1,
                                       uint32_t& r2, uint32_t& r3, uint32_t a) {
    asm volatile("ldmatrix.sync.aligned.m8n8.x4.trans.shared.b16 {%0,%1,%2,%3}, [%4];"
                 : "=r"(r0), "=r"(r1), "=r"(r2), "=r"(r3) : "r"(a));
}
__device__ __forceinline__ void mma_f16(float c[4],
    uint32_t a0, uint32_t a1, uint32_t a2, uint32_t a3,
    uint32_t b0, uint32_t b1) {
    asm volatile("mma.sync.aligned.m16n8k16.row.col.f32.f16.f16.f32 "
                 "{%0,%1,%2,%3}, {%4,%5,%6,%7}, {%8,%9}, {%0,%1,%2,%3};"
                 : "+f"(c[0]), "+f"(c[1]), "+f"(c[2]), "+f"(c[3])
                 : "r"(a0), "r"(a1), "r"(a2), "r"(a3), "r"(b0), "r"(b1));
}
__device__ __forceinline__ void cp16(uint32_t dst, const void* src) {
    asm volatile("cp.async.cg.shared.global [%0], [%1], 16;"
                 :: "r"(dst), "l"(src));
}
#define CP_COMMIT() asm volatile("cp.async.commit_group;")
#define CP_WAIT(n)  asm volatile("cp.async.wait_group %0;" :: "n"(n))

__device__ __forceinline__ float ex2(float x) {
    float r; asm("ex2.approx.ftz.f32 %0, %1;" : "=f"(r) : "f"(x));
    return r;
}
// packed fp16 exp2 (one MUFU op for two values)
__device__ __forceinline__ uint32_t ex2h2(uint32_t x) {
    uint32_t r; asm("ex2.approx.f16x2 %0, %1;" : "=r"(r) : "r"(x));
    return r;
}
// pack two fp32 -> fp16x2 (lo half = first arg)
__device__ __forceinline__ uint32_t packh2(float lo, float hi) {
    uint32_t r;
    asm("cvt.rn.f16x2.f32 %0, %1, %2;" : "=r"(r) : "f"(hi), "f"(lo));
    return r;
}
// fp32 pair -> fp16 hi/lo packed pairs
__device__ __forceinline__ void hilo2h(float x, float y,
                                       uint32_t& h, uint32_t& l) {
    __half2 hh = __floats2half2_rn(x, y);
    float2 hf = __half22float2(hh);
    __half2 ll = __floats2half2_rn(x - hf.x, y - hf.y);
    h = *reinterpret_cast<uint32_t*>(&hh);
    l = *reinterpret_cast<uint32_t*>(&ll);
}

// ---- Scratch ----
__device__ f16 g_xh[3 * XSZ];
__device__ f16 g_xl[3 * XSZ];
__device__ f16 g_yh[3 * XSZ];      // Q/K/V projections, fp16-hi only
__device__ f16 g_wth[4 * WSZ];
__device__ f16 g_wtl[4 * WSZ];

// ---------------------------------------------------------------------------
// fp32 -> fp16 hi/lo split (3 inputs fused)
// ---------------------------------------------------------------------------
__global__ __launch_bounds__(256) void xconv3(
    const float* __restrict__ X0, const float* __restrict__ X1,
    const float* __restrict__ X2, f16* __restrict__ xh, f16* __restrict__ xl)
{
    const int z = blockIdx.z;
    const float* X = (z == 0) ? X0 : (z == 1) ? X1 : X2;
    const size_t i4 = ((size_t)blockIdx.x * 256 + threadIdx.x) * 4;
    const float4 v = *reinterpret_cast<const float4*>(X + i4);
    uint32_t h0, l0, h1, l1;
    hilo2h(v.x, v.y, h0, l0);
    hilo2h(v.z, v.w, h1, l1);
    const size_t o = (size_t)z * XSZ + i4;
    *reinterpret_cast<uint2*>(xh + o) = make_uint2(h0, h1);
    *reinterpret_cast<uint2*>(xl + o) = make_uint2(l0, l1);
}

// ---------------------------------------------------------------------------
// W[K,N] fp32 -> W^T[N,K] fp16 hi/lo
// ---------------------------------------------------------------------------
__global__ __launch_bounds__(256) void wconv(
    const float* __restrict__ W0, const float* __restrict__ W1,
    const float* __restrict__ W2, const float* __restrict__ W3,
    f16* __restrict__ wh, f16* __restrict__ wl)
{
    __shared__ float t[32][33];
    const int z = blockIdx.z;
    const float* W = (z == 0) ? W0 : (z == 1) ? W1 : (z == 2) ? W2 : W3;
    const int n0 = blockIdx.x * 32, k0 = blockIdx.y * 32;
    const int tx = threadIdx.x, ty = threadIdx.y;
    #pragma unroll
    for (int i = 0; i < 4; i++)
        t[ty + 8 * i][tx] = W[(size_t)(k0 + ty + 8 * i) * cHD + n0 + tx];
    __syncthreads();
    const size_t zb = (size_t)z * WSZ;
    #pragma unroll
    for (int i = 0; i < 4; i++) {
        const float v = t[tx][ty + 8 * i];
        const f16 h = __float2half_rn(v);
        const f16 l = __float2half_rn(v - __half2float(h));
        const size_t o = zb + (size_t)(n0 + ty + 8 * i) * cD + k0 + tx;
        wh[o] = h; wl[o] = l;
    }
}

// ---------------------------------------------------------------------------
// mma.sync split-fp16 GEMM (verified). Per-z: 3-term or 2-term (W-lo dropped).
// ---------------------------------------------------------------------------
constexpr int ROWB = 80;
constexpr int TILE_B = 128 * ROWB;
constexpr int STAGE_B = 4 * TILE_B;
constexpr int GEMM_SMEM = 2 * STAGE_B;   // 81920

template <bool F16OUT>
__global__ __launch_bounds__(256, 2) void gemm_mma(
    const f16* __restrict__ Xh, const f16* __restrict__ Xl,
    const f16* __restrict__ Wh, const f16* __restrict__ Wl,
    const float* b0, const float* b1, const float* b2,
    float* oF, f16* oh, float scale0, int term2_mask)
{
    extern __shared__ char dynsm[];
    const uint32_t sb = smem_u32(dynsm);
    const int tid = threadIdx.x;
    const int wid = tid >> 5;
    const int lane = tid & 31;
    const int z = blockIdx.z;
    const int m0 = blockIdx.y * 128;
    const int n0 = blockIdx.x * 128;
    const int wm = wid & 1;
    const int wn = wid >> 1;

    const f16* Ah = Xh + (size_t)z * XSZ;
    const f16* Al = Xl + (size_t)z * XSZ;
    const f16* Bh = Wh + (size_t)z * WSZ;
    const f16* Bl = Wl + (size_t)z * WSZ;
    const float* bias = (z == 0) ? b0 : (z == 1) ? b1 : b2;
    const float scale = (z == 0) ? scale0 : 1.0f;
    const bool two_term = ((term2_mask >> z) & 1) != 0;

    float acc[4][4][4] = {};

    const int lr0 = tid >> 2, lc = (tid & 3);
    const uint32_t so0 = (uint32_t)(lr0 * ROWB + lc * 16);
    const uint32_t so1 = (uint32_t)((lr0 + 64) * ROWB + lc * 16);

    auto load_stage = [&](int chunk, int stage) {
        const uint32_t s0 = sb + stage * STAGE_B;
        const int k0 = chunk * 32;
        const size_t ga0 = (size_t)(m0 + lr0) * cD + k0 + lc * 8;
        const size_t ga1 = (size_t)(m0 + lr0 + 64) * cD + k0 + lc * 8;
        const size_t gb0 = (size_t)(n0 + lr0) * cD + k0 + lc * 8;
        const size_t gb1 = (size_t)(n0 + lr0 + 64) * cD + k0 + lc * 8;
        cp16(s0 + so0,              Ah + ga0);
        cp16(s0 + so1,              Ah + ga1);
        cp16(s0 + TILE_B + so0,     Al + ga0);
        cp16(s0 + TILE_B + so1,     Al + ga1);
        cp16(s0 + 2 * TILE_B + so0, Bh + gb0);
        cp16(s0 + 2 * TILE_B + so1, Bh + gb1);
        if (!two_term) {
            cp16(s0 + 3 * TILE_B + so0, Bl + gb0);
            cp16(s0 + 3 * TILE_B + so1, Bl + gb1);
        }
        CP_COMMIT();
    };

    load_stage(0, 0);
    const int NCH = cD / 32;
    for (int ch = 0; ch < NCH; ch++) {
        if (ch + 1 < NCH) { load_stage(ch + 1, (ch + 1) & 1); CP_WAIT(1); }
        else              { CP_WAIT(0); }
        __syncthreads();
        const uint32_t s0 = sb + (ch & 1) * STAGE_B;

        #pragma unroll
        for (int ks = 0; ks < 2; ks++) {
            const int acol = ks * 16 + ((lane >> 4) << 3);
            const int bcol = ks * 16 + (((lane >> 3) & 1) << 3);
            const int brow0 = wn * 32 + (lane & 7) + ((lane >> 4) << 3);

            // B-hi fragments
            uint32_t bh[4][2];
            #pragma unroll
            for (int np = 0; np < 2; np++) {
                const uint32_t boff = (uint32_t)((brow0 + np * 16) * ROWB + bcol * 2);
                uint32_t r0, r1, r2, r3;
                ldsm4(r0, r1, r2, r3, s0 + 2 * TILE_B + boff);
                bh[2 * np][0] = r0;     bh[2 * np][1] = r1;
                bh[2 * np + 1][0] = r2; bh[2 * np + 1][1] = r3;
            }
            // A-hi fragments
            uint32_t af[4][4];
            #pragma unroll
            for (int mi = 0; mi < 4; mi++) {
                const int row = wm * 64 + mi * 16 + (lane & 15);
                ldsm4(af[mi][0], af[mi][1], af[mi][2], af[mi][3],
                      s0 + (uint32_t)(row * ROWB + acol * 2));
            }
            #pragma unroll
            for (int mi = 0; mi < 4; mi++)
                #pragma unroll
                for (int ni = 0; ni < 4; ni++)
                    mma_f16(acc[mi][ni], af[mi][0], af[mi][1],
                            af[mi][2], af[mi][3], bh[ni][0], bh[ni][1]);

            if (!two_term) {
                uint32_t bl[4][2];
                #pragma unroll
                for (int np = 0; np < 2; np++) {
                    const uint32_t boff = (uint32_t)((brow0 + np * 16) * ROWB + bcol * 2);
                    uint32_t r0, r1, r2, r3;
                    ldsm4(r0, r1, r2, r3, s0 + 3 * TILE_B + boff);
                    bl[2 * np][0] = r0;     bl[2 * np][1] = r1;
                    bl[2 * np + 1][0] = r2; bl[2 * np + 1][1] = r3;
                }
                #pragma unroll
                for (int mi = 0; mi < 4; mi++)
                    #pragma unroll
                    for (int ni = 0; ni < 4; ni++)
                        mma_f16(acc[mi][ni], af[mi][0], af[mi][1],
                                af[mi][2], af[mi][3], bl[ni][0], bl[ni][1]);
            }

            // A-lo overwrites the same registers; multiply with B-hi
            #pragma unroll
            for (int mi = 0; mi < 4; mi++) {
                const int row = wm * 64 + mi * 16 + (lane & 15);
                ldsm4(af[mi][0], af[mi][1], af[mi][2], af[mi][3],
                      s0 + TILE_B + (uint32_t)(row * ROWB + acol * 2));
            }
            #pragma unroll
            for (int mi = 0; mi < 4; mi++)
                #pragma unroll
                for (int ni = 0; ni < 4; ni++)
                    mma_f16(acc[mi][ni], af[mi][0], af[mi][1],
                            af[mi][2], af[mi][3], bh[ni][0], bh[ni][1]);
        }
        __syncthreads();
    }

    #pragma unroll
    for (int mi = 0; mi < 4; mi++) {
        #pragma unroll
        for (int h = 0; h < 2; h++) {
            const int row = m0 + wm * 64 + mi * 16 + h * 8 + (lane >> 2);
            #pragma unroll
            for (int ni = 0; ni < 4; ni++) {
                const int col = n0 + wn * 32 + ni * 8 + (lane & 3) * 2;
                const float2 bb = *reinterpret_cast<const float2*>(bias + col);
                const float v0 = (acc[mi][ni][h * 2 + 0] + bb.x) * scale;
                const float v1 = (acc[mi][ni][h * 2 + 1] + bb.y) * scale;
                if (F16OUT) {
                    const size_t o = (size_t)z * XSZ + (size_t)row * 1024 + col;
                    *reinterpret_cast<uint32_t*>(oh + o) = packh2(v0, v1);
                } else {
                    *reinterpret_cast<float2*>(oF + (size_t)row * 1024 + col) =
                        make_float2(v0, v1);
                }
            }
        }
    }
}

// ---------------------------------------------------------------------------
// fp16 flash attention v5 (pure-hi Q path):
//   S = Qh*Kh (1-term);  P = ex2.f16x2(S - m);  O += Ph*Vh
//   row sums via ones-MMA; 4-stage cp.async K/V pipeline.
// ---------------------------------------------------------------------------
constexpr int ROW2 = 144;
constexpr int R_KH = 0;
constexpr int R_VH = 64 * ROW2;
constexpr int STG2 = 2 * 64 * ROW2;          // 18432 per stage
constexpr int ATTN_SMEM = 4 * STG2;          // 73728

__global__ __launch_bounds__(256, 2) void attn_mma(
    const f16* __restrict__ qh, const f16* __restrict__ kh,
    const f16* __restrict__ vh, f16* __restrict__ oh, f16* __restrict__ ol)
{
    __shared__ __align__(16) unsigned char smb[ATTN_SMEM];
    const uint32_t sb = smem_u32(smb);
    const int tid = threadIdx.x;
    const int wid = tid >> 5;
    const int lane = tid & 31;
    const int t0 = blockIdx.x * 128;
    const int hh = blockIdx.y;
    const int bi = blockIdx.z;

    // ---- Q-hi staged transiently in the stage area, then to registers
    #pragma unroll
    for (int it = 0; it < 4; it++) {
        const int i = tid + it * 256;
        const int r = i >> 3, c = i & 7;
        const size_t g = ((size_t)(bi * cT + t0 + r) * cH + hh) * cDK + c * 8;
        *reinterpret_cast<uint4*>(smb + r * ROW2 + c * 16) =
            *reinterpret_cast<const uint4*>(qh + g);
    }
    __syncthreads();

    uint32_t qfh[4][4];
    #pragma unroll
    for (int kb = 0; kb < 4; kb++) {
        const int row = wid * 16 + (lane & 15);
        const int col = kb * 16 + ((lane >> 4) << 3);
        ldsm4(qfh[kb][0], qfh[kb][1], qfh[kb][2], qfh[kb][3],
              sb + (uint32_t)(row * ROW2 + col * 2));
    }
    __syncthreads();   // stage area free for K/V

    const int lr = tid >> 3, lc8 = (tid & 7);
    auto load_kv = [&](int s0, int stage) {
        const uint32_t st = sb + stage * STG2;
        #pragma unroll
        for (int it = 0; it < 2; it++) {
            const int r = lr + it * 32;
            const uint32_t so = (uint32_t)(r * ROW2 + lc8 * 16);
            const size_t g = ((size_t)(bi * cS + s0 + r) * cH + hh) * cDK + lc8 * 8;
            cp16(st + R_KH + so, kh + g);
            cp16(st + R_VH + so, vh + g);
        }
        CP_COMMIT();
    };

    float oacc[8][4] = {};
    float mrow0 = -INFINITY, mrow1 = -INFINITY;
    float lrow0 = 0.0f, lrow1 = 0.0f;

    const int quad = lane >> 3, id8 = lane & 7;
    constexpr uint32_t ONES2 = 0x3C003C00u;   // half2(1.0, 1.0)
    constexpr int NT = cS / 64;

    load_kv(0, 0);
    load_kv(64, 1);
    load_kv(128, 2);

    for (int ch = 0; ch < NT; ch++) {
        CP_WAIT(2);
        __syncthreads();
        const uint32_t st = sb + (ch & 3) * STG2;

        // ---- S = Qh*Kh (1-term)
        float sacc[8][4] = {};
        #pragma unroll
        for (int kb = 0; kb < 4; kb++) {
            #pragma unroll
            for (int np = 0; np < 4; np++) {
                const int nrow = np * 16 + (lane & 7) + ((lane >> 4) << 3);
                const int col = kb * 16 + (((lane >> 3) & 1) << 3);
                uint32_t h0, h1, h2, h3;
                ldsm4(h0, h1, h2, h3, st + (uint32_t)(R_KH + nrow * ROW2 + col * 2));
                mma_f16(sacc[2 * np], qfh[kb][0], qfh[kb][1], qfh[kb][2], qfh[kb][3], h0, h1);
                mma_f16(sacc[2 * np + 1], qfh[kb][0], qfh[kb][1], qfh[kb][2], qfh[kb][3], h2, h3);
            }
        }

        // prefetch tile ch+3 now so cp.async overlaps softmax + PV
        if (ch + 3 < NT) load_kv((ch + 3) * 64, (ch + 3) & 3);
        else             CP_COMMIT();

        // ---- max reduction (fp32)
        float mx0 = -INFINITY, mx1 = -INFINITY;
        #pragma unroll
        for (int n = 0; n < 8; n++) {
            mx0 = fmaxf(mx0, fmaxf(sacc[n][0], sacc[n][1]));
            mx1 = fmaxf(mx1, fmaxf(sacc[n][2], sacc[n][3]));
        }
        mx0 = fmaxf(mx0, __shfl_xor_sync(0xffffffffu, mx0, 1));
        mx0 = fmaxf(mx0, __shfl_xor_sync(0xffffffffu, mx0, 2));
        mx1 = fmaxf(mx1, __shfl_xor_sync(0xffffffffu, mx1, 1));
        mx1 = fmaxf(mx1, __shfl_xor_sync(0xffffffffu, mx1, 2));
        const float mn0 = fmaxf(mrow0, mx0);
        const float mn1 = fmaxf(mrow1, mx1);
        const float corr0 = ex2(mrow0 - mn0);
        const float corr1 = ex2(mrow1 - mn1);
        mrow0 = mn0;  mrow1 = mn1;

        // ---- P = ex2(S - m) in packed fp16; row sums via ones-MMA
        uint32_t pah[4][4];
        float sumacc[4] = {0.f, 0.f, 0.f, 0.f};
        #pragma unroll
        for (int kb = 0; kb < 4; kb++) {
            pah[kb][0] = ex2h2(packh2(sacc[2 * kb][0] - mn0, sacc[2 * kb][1] - mn0));
            pah[kb][1] = ex2h2(packh2(sacc[2 * kb][2] - mn1, sacc[2 * kb][3] - mn1));
            pah[kb][2] = ex2h2(packh2(sacc[2 * kb + 1][0] - mn0, sacc[2 * kb + 1][1] - mn0));
            pah[kb][3] = ex2h2(packh2(sacc[2 * kb + 1][2] - mn1, sacc[2 * kb + 1][3] - mn1));
            mma_f16(sumacc, pah[kb][0], pah[kb][1], pah[kb][2], pah[kb][3],
                    ONES2, ONES2);
        }
        lrow0 = lrow0 * corr0 + sumacc[0];
        lrow1 = lrow1 * corr1 + sumacc[2];

        #pragma unroll
        for (int n = 0; n < 8; n++) {
            oacc[n][0] *= corr0; oacc[n][1] *= corr0;
            oacc[n][2] *= corr1; oacc[n][3] *= corr1;
        }

        // ---- O += Ph*Vh (V natural, trans-ldsm B-fragments)
        #pragma unroll
        for (int kb = 0; kb < 4; kb++) {
            #pragma unroll
            for (int np = 0; np < 4; np++) {
                const uint32_t av = (uint32_t)(
                    (kb * 16 + (quad & 1) * 8 + id8) * ROW2 +
                    (np * 16 + (quad >> 1) * 8) * 2);
                uint32_t h0, h1, h2, h3;
                ldsm4t(h0, h1, h2, h3, st + R_VH + av);
                mma_f16(oacc[2 * np], pah[kb][0], pah[kb][1], pah[kb][2], pah[kb][3], h0, h1);
                mma_f16(oacc[2 * np + 1], pah[kb][0], pah[kb][1], pah[kb][2], pah[kb][3], h2, h3);
            }
        }
    }

    // ---- Normalize + write O as fp16 hi/lo
    const float inv0 = 1.0f / lrow0;
    const float inv1 = 1.0f / lrow1;
    const int row0 = t0 + wid * 16 + (lane >> 2);
    #pragma unroll
    for (int n = 0; n < 8; n++) {
        const int dk = n * 8 + (lane & 3) * 2;
        const size_t g0 = ((size_t)(bi * cT + row0) * cH + hh) * cDK + dk;
        const size_t g1 = ((size_t)(bi * cT + row0 + 8) * cH + hh) * cDK + dk;
        uint32_t hp, lp;
        hilo2h(oacc[n][0] * inv0, oacc[n][1] * inv0, hp, lp);
        *reinterpret_cast<uint32_t*>(oh + g0) = hp;
        *reinterpret_cast<uint32_t*>(ol + g0) = lp;
        hilo2h(oacc[n][2] * inv1, oacc[n][3] * inv1, hp, lp);
        *reinterpret_cast<uint32_t*>(oh + g1) = hp;
        *reinterpret_cast<uint32_t*>(ol + g1) = lp;
    }
}

// ---------------------------------------------------------------------------
extern "C" void kernel_launch(void* const* d_in, const int* in_sizes, int n_in,
                              void* d_out, int out_size)
{
    const float* query = (const float*)d_in[0];
    const float* value = (const float*)d_in[1];
    const float* key   = (const float*)d_in[2];
    const float* Wq    = (const float*)d_in[3];
    const float* bq    = (const float*)d_in[4];
    const float* Wk    = (const float*)d_in[5];
    const float* bk    = (const float*)d_in[6];
    const float* Wv    = (const float*)d_in[7];
    const float* bv    = (const float*)d_in[8];
    const float* Wo    = (const float*)d_in[9];
    const float* bo    = (const float*)d_in[10];
    float* out = (float*)d_out;

    f16 *xh, *xl, *yh, *wh, *wl;
    cudaGetSymbolAddress((void**)&xh, g_xh);
    cudaGetSymbolAddress((void**)&xl, g_xl);
    cudaGetSymbolAddress((void**)&yh, g_yh);
    cudaGetSymbolAddress((void**)&wh, g_wth);
    cudaGetSymbolAddress((void**)&wl, g_wtl);

    cudaFuncSetAttribute(gemm_mma<true>,
                         cudaFuncAttributeMaxDynamicSharedMemorySize, GEMM_SMEM);
    cudaFuncSetAttribute(gemm_mma<false>,
                         cudaFuncAttributeMaxDynamicSharedMemorySize, GEMM_SMEM);

    const int XB = (int)(XSZ / 4 / 256);

    xconv3<<<dim3(XB, 1, 3), 256>>>(query, key, value, xh, xl);
    wconv<<<dim3(32, 32, 4), dim3(32, 8)>>>(Wq, Wk, Wv, Wo, wh, wl);

    // Q/K/V projections, all 2-term (Xh*Wh + Xl*Wh), fp16-hi outputs only;
    // Q scaled by 1/sqrt(DK)*log2(e)
    const float qscale = 0.125f * 1.44269504088896340736f;
    gemm_mma<true><<<dim3(cHD / 128, cMT / 128, 3), 256, GEMM_SMEM>>>(
        xh, xl, wh, wl, bq, bk, bv, nullptr, yh, qscale, 0b111);

    // 1-term fp16 attention; out -> x slot 0 hi/lo
    attn_mma<<<dim3(cT / 128, cH, cB), 256>>>(
        yh, yh + XSZ, yh + 2 * XSZ, xh, xl);

    // O projection (fp32 out, 2-term: Xh*Wh + Xl*Wh — W-lo now below the
    // noise floor of the attention output flowing through it)
    gemm_mma<false><<<dim3(cD / 128, cMT / 128, 1), 256, GEMM_SMEM>>>(
        xh, xl, wh + 3 * WSZ, wl + 3 * WSZ, bo, bo, bo, out, nullptr,
        1.0f, 1);
}

// round 16
// speedup vs baseline: 1.5114x; 1.5114x over previous
#include <cuda_runtime.h>
#include <cuda_fp16.h>
#include <math.h>
#include <cstdint>

// Problem constants
constexpr int cB = 2, cT = 2048, cS = 2048, cD = 1024, cH = 16, cDK = 64;
constexpr int cHD = cH * cDK;      // 1024
constexpr int cMT = cB * cT;       // 4096
constexpr size_t XSZ = (size_t)cMT * cD;
constexpr size_t WSZ = (size_t)cD * cHD;

using f16 = __half;

// ---- helpers ----
__device__ __forceinline__ uint32_t smem_u32(const void* p) {
    uint32_t a;
    asm("{ .reg .u64 t; cvta.to.shared.u64 t, %1; cvt.u32.u64 %0, t; }"
        : "=r"(a) : "l"(p));
    return a;
}
__device__ __forceinline__ void ldsm4(uint32_t& r0, uint32_t& r1,
                                      uint32_t& r2, uint32_t& r3, uint32_t a) {
    asm volatile("ldmatrix.sync.aligned.m8n8.x4.shared.b16 {%0,%1,%2,%3}, [%4];"
                 : "=r"(r0), "=r"(r1), "=r"(r2), "=r"(r3) : "r"(a));
}
__device__ __forceinline__ void ldsm4t(uint32_t& r0, uint32_t& r1,
                                       uint32_t& r2, uint32_t& r3, uint32_t a) {
    asm volatile("ldmatrix.sync.aligned.m8n8.x4.trans.shared.b16 {%0,%1,%2,%3}, [%4];"
                 : "=r"(r0), "=r"(r1), "=r"(r2), "=r"(r3) : "r"(a));
}
__device__ __forceinline__ void mma_f16(float c[4],
    uint32_t a0, uint32_t a1, uint32_t a2, uint32_t a3,
    uint32_t b0, uint32_t b1) {
    asm volatile("mma.sync.aligned.m16n8k16.row.col.f32.f16.f16.f32 "
                 "{%0,%1,%2,%3}, {%4,%5,%6,%7}, {%8,%9}, {%0,%1,%2,%3};"
                 : "+f"(c[0]), "+f"(c[1]), "+f"(c[2]), "+f"(c[3])
                 : "r"(a0), "r"(a1), "r"(a2), "r"(a3), "r"(b0), "r"(b1));
}
__device__ __forceinline__ void cp16(uint32_t dst, const void* src) {
    asm volatile("cp.async.cg.shared.global [%0], [%1], 16;"
                 :: "r"(dst), "l"(src));
}
#define CP_COMMIT() asm volatile("cp.async.commit_group;")
#define CP_WAIT(n)  asm volatile("cp.async.wait_group %0;" :: "n"(n))

__device__ __forceinline__ float ex2(float x) {
    float r; asm("ex2.approx.ftz.f32 %0, %1;" : "=f"(r) : "f"(x));
    return r;
}
// packed fp16 exp2 (one MUFU op for two values)
__device__ __forceinline__ uint32_t ex2h2(uint32_t x) {
    uint32_t r; asm("ex2.approx.f16x2 %0, %1;" : "=r"(r) : "r"(x));
    return r;
}
// pack two fp32 -> fp16x2 (lo half = first arg)
__device__ __forceinline__ uint32_t packh2(float lo, float hi) {
    uint32_t r;
    asm("cvt.rn.f16x2.f32 %0, %1, %2;" : "=r"(r) : "f"(hi), "f"(lo));
    return r;
}
// fp32 pair -> fp16 hi/lo packed pairs
__device__ __forceinline__ void hilo2h(float x, float y,
                                       uint32_t& h, uint32_t& l) {
    __half2 hh = __floats2half2_rn(x, y);
    float2 hf = __half22float2(hh);
    __half2 ll = __floats2half2_rn(x - hf.x, y - hf.y);
    h = *reinterpret_cast<uint32_t*>(&hh);
    l = *reinterpret_cast<uint32_t*>(&ll);
}

// ---- Scratch ----
__device__ f16 g_xh[3 * XSZ];
__device__ f16 g_xl[3 * XSZ];
__device__ f16 g_yh[3 * XSZ];      // Q/K/V projections, fp16-hi only
__device__ f16 g_wth[4 * WSZ];
__device__ f16 g_wtl[4 * WSZ];

// ---------------------------------------------------------------------------
// fp32 -> fp16 hi/lo split (3 inputs fused)
// ---------------------------------------------------------------------------
__global__ __launch_bounds__(256) void xconv3(
    const float* __restrict__ X0, const float* __restrict__ X1,
    const float* __restrict__ X2, f16* __restrict__ xh, f16* __restrict__ xl)
{
    const int z = blockIdx.z;
    const float* X = (z == 0) ? X0 : (z == 1) ? X1 : X2;
    const size_t i4 = ((size_t)blockIdx.x * 256 + threadIdx.x) * 4;
    const float4 v = *reinterpret_cast<const float4*>(X + i4);
    uint32_t h0, l0, h1, l1;
    hilo2h(v.x, v.y, h0, l0);
    hilo2h(v.z, v.w, h1, l1);
    const size_t o = (size_t)z * XSZ + i4;
    *reinterpret_cast<uint2*>(xh + o) = make_uint2(h0, h1);
    *reinterpret_cast<uint2*>(xl + o) = make_uint2(l0, l1);
}

// ---------------------------------------------------------------------------
// W[K,N] fp32 -> W^T[N,K] fp16 hi/lo
// ---------------------------------------------------------------------------
__global__ __launch_bounds__(256) void wconv(
    const float* __restrict__ W0, const float* __restrict__ W1,
    const float* __restrict__ W2, const float* __restrict__ W3,
    f16* __restrict__ wh, f16* __restrict__ wl)
{
    __shared__ float t[32][33];
    const int z = blockIdx.z;
    const float* W = (z == 0) ? W0 : (z == 1) ? W1 : (z == 2) ? W2 : W3;
    const int n0 = blockIdx.x * 32, k0 = blockIdx.y * 32;
    const int tx = threadIdx.x, ty = threadIdx.y;
    #pragma unroll
    for (int i = 0; i < 4; i++)
        t[ty + 8 * i][tx] = W[(size_t)(k0 + ty + 8 * i) * cHD + n0 + tx];
    __syncthreads();
    const size_t zb = (size_t)z * WSZ;
    #pragma unroll
    for (int i = 0; i < 4; i++) {
        const float v = t[tx][ty + 8 * i];
        const f16 h = __float2half_rn(v);
        const f16 l = __float2half_rn(v - __half2float(h));
        const size_t o = zb + (size_t)(n0 + ty + 8 * i) * cD + k0 + tx;
        wh[o] = h; wl[o] = l;
    }
}

// ---------------------------------------------------------------------------
// mma.sync split-fp16 GEMM (verified). Per-z: 3-term or 2-term (W-lo dropped).
// ---------------------------------------------------------------------------
constexpr int ROWB = 80;
constexpr int TILE_B = 128 * ROWB;
constexpr int STAGE_B = 4 * TILE_B;
constexpr int GEMM_SMEM = 2 * STAGE_B;   // 81920

template <bool F16OUT>
__global__ __launch_bounds__(256, 2) void gemm_mma(
    const f16* __restrict__ Xh, const f16* __restrict__ Xl,
    const f16* __restrict__ Wh, const f16* __restrict__ Wl,
    const float* b0, const float* b1, const float* b2,
    float* oF, f16* oh, float scale0, int term2_mask)
{
    extern __shared__ char dynsm[];
    const uint32_t sb = smem_u32(dynsm);
    const int tid = threadIdx.x;
    const int wid = tid >> 5;
    const int lane = tid & 31;
    const int z = blockIdx.z;
    const int m0 = blockIdx.y * 128;
    const int n0 = blockIdx.x * 128;
    const int wm = wid & 1;
    const int wn = wid >> 1;

    const f16* Ah = Xh + (size_t)z * XSZ;
    const f16* Al = Xl + (size_t)z * XSZ;
    const f16* Bh = Wh + (size_t)z * WSZ;
    const f16* Bl = Wl + (size_t)z * WSZ;
    const float* bias = (z == 0) ? b0 : (z == 1) ? b1 : b2;
    const float scale = (z == 0) ? scale0 : 1.0f;
    const bool two_term = ((term2_mask >> z) & 1) != 0;

    float acc[4][4][4] = {};

    const int lr0 = tid >> 2, lc = (tid & 3);
    const uint32_t so0 = (uint32_t)(lr0 * ROWB + lc * 16);
    const uint32_t so1 = (uint32_t)((lr0 + 64) * ROWB + lc * 16);

    auto load_stage = [&](int chunk, int stage) {
        const uint32_t s0 = sb + stage * STAGE_B;
        const int k0 = chunk * 32;
        const size_t ga0 = (size_t)(m0 + lr0) * cD + k0 + lc * 8;
        const size_t ga1 = (size_t)(m0 + lr0 + 64) * cD + k0 + lc * 8;
        const size_t gb0 = (size_t)(n0 + lr0) * cD + k0 + lc * 8;
        const size_t gb1 = (size_t)(n0 + lr0 + 64) * cD + k0 + lc * 8;
        cp16(s0 + so0,              Ah + ga0);
        cp16(s0 + so1,              Ah + ga1);
        cp16(s0 + TILE_B + so0,     Al + ga0);
        cp16(s0 + TILE_B + so1,     Al + ga1);
        cp16(s0 + 2 * TILE_B + so0, Bh + gb0);
        cp16(s0 + 2 * TILE_B + so1, Bh + gb1);
        if (!two_term) {
            cp16(s0 + 3 * TILE_B + so0, Bl + gb0);
            cp16(s0 + 3 * TILE_B + so1, Bl + gb1);
        }
        CP_COMMIT();
    };

    load_stage(0, 0);
    const int NCH = cD / 32;
    for (int ch = 0; ch < NCH; ch++) {
        if (ch + 1 < NCH) { load_stage(ch + 1, (ch + 1) & 1); CP_WAIT(1); }
        else              { CP_WAIT(0); }
        __syncthreads();
        const uint32_t s0 = sb + (ch & 1) * STAGE_B;

        #pragma unroll
        for (int ks = 0; ks < 2; ks++) {
            const int acol = ks * 16 + ((lane >> 4) << 3);
            const int bcol = ks * 16 + (((lane >> 3) & 1) << 3);
            const int brow0 = wn * 32 + (lane & 7) + ((lane >> 4) << 3);

            // B-hi fragments
            uint32_t bh[4][2];
            #pragma unroll
            for (int np = 0; np < 2; np++) {
                const uint32_t boff = (uint32_t)((brow0 + np * 16) * ROWB + bcol * 2);
                uint32_t r0, r1, r2, r3;
                ldsm4(r0, r1, r2, r3, s0 + 2 * TILE_B + boff);
                bh[2 * np][0] = r0;     bh[2 * np][1] = r1;
                bh[2 * np + 1][0] = r2; bh[2 * np + 1][1] = r3;
            }
            // A-hi fragments
            uint32_t af[4][4];
            #pragma unroll
            for (int mi = 0; mi < 4; mi++) {
                const int row = wm * 64 + mi * 16 + (lane & 15);
                ldsm4(af[mi][0], af[mi][1], af[mi][2], af[mi][3],
                      s0 + (uint32_t)(row * ROWB + acol * 2));
            }
            #pragma unroll
            for (int mi = 0; mi < 4; mi++)
                #pragma unroll
                for (int ni = 0; ni < 4; ni++)
                    mma_f16(acc[mi][ni], af[mi][0], af[mi][1],
                            af[mi][2], af[mi][3], bh[ni][0], bh[ni][1]);

            if (!two_term) {
                uint32_t bl[4][2];
                #pragma unroll
                for (int np = 0; np < 2; np++) {
                    const uint32_t boff = (uint32_t)((brow0 + np * 16) * ROWB + bcol * 2);
                    uint32_t r0, r1, r2, r3;
                    ldsm4(r0, r1, r2, r3, s0 + 3 * TILE_B + boff);
                    bl[2 * np][0] = r0;     bl[2 * np][1] = r1;
                    bl[2 * np + 1][0] = r2; bl[2 * np + 1][1] = r3;
                }
                #pragma unroll
                for (int mi = 0; mi < 4; mi++)
                    #pragma unroll
                    for (int ni = 0; ni < 4; ni++)
                        mma_f16(acc[mi][ni], af[mi][0], af[mi][1],
                                af[mi][2], af[mi][3], bl[ni][0], bl[ni][1]);
            }

            // A-lo overwrites the same registers; multiply with B-hi
            #pragma unroll
            for (int mi = 0; mi < 4; mi++) {
                const int row = wm * 64 + mi * 16 + (lane & 15);
                ldsm4(af[mi][0], af[mi][1], af[mi][2], af[mi][3],
                      s0 + TILE_B + (uint32_t)(row * ROWB + acol * 2));
            }
            #pragma unroll
            for (int mi = 0; mi < 4; mi++)
                #pragma unroll
                for (int ni = 0; ni < 4; ni++)
                    mma_f16(acc[mi][ni], af[mi][0], af[mi][1],
                            af[mi][2], af[mi][3], bh[ni][0], bh[ni][1]);
        }
        __syncthreads();
    }

    #pragma unroll
    for (int mi = 0; mi < 4; mi++) {
        #pragma unroll
        for (int h = 0; h < 2; h++) {
            const int row = m0 + wm * 64 + mi * 16 + h * 8 + (lane >> 2);
            #pragma unroll
            for (int ni = 0; ni < 4; ni++) {
                const int col = n0 + wn * 32 + ni * 8 + (lane & 3) * 2;
                const float2 bb = *reinterpret_cast<const float2*>(bias + col);
                const float v0 = (acc[mi][ni][h * 2 + 0] + bb.x) * scale;
                const float v1 = (acc[mi][ni][h * 2 + 1] + bb.y) * scale;
                if (F16OUT) {
                    const size_t o = (size_t)z * XSZ + (size_t)row * 1024 + col;
                    *reinterpret_cast<uint32_t*>(oh + o) = packh2(v0, v1);
                } else {
                    *reinterpret_cast<float2*>(oF + (size_t)row * 1024 + col) =
                        make_float2(v0, v1);
                }
            }
        }
    }
}

// ---------------------------------------------------------------------------
// fp16 flash attention v5 (pure-hi Q path):
//   S = Qh*Kh (1-term);  P = ex2.f16x2(S - m);  O += Ph*Vh
//   row sums via ones-MMA; 4-stage cp.async K/V pipeline.
// ---------------------------------------------------------------------------
constexpr int ROW2 = 144;
constexpr int R_KH = 0;
constexpr int R_VH = 64 * ROW2;
constexpr int STG2 = 2 * 64 * ROW2;          // 18432 per stage
constexpr int ATTN_SMEM = 4 * STG2;          // 73728

__global__ __launch_bounds__(256, 2) void attn_mma(
    const f16* __restrict__ qh, const f16* __restrict__ kh,
    const f16* __restrict__ vh, f16* __restrict__ oh, f16* __restrict__ ol)
{
    __shared__ __align__(16) unsigned char smb[ATTN_SMEM];
    const uint32_t sb = smem_u32(smb);
    const int tid = threadIdx.x;
    const int wid = tid >> 5;
    const int lane = tid & 31;
    const int t0 = blockIdx.x * 128;
    const int hh = blockIdx.y;
    const int bi = blockIdx.z;

    // ---- Q-hi staged transiently in the stage area, then to registers
    #pragma unroll
    for (int it = 0; it < 4; it++) {
        const int i = tid + it * 256;
        const int r = i >> 3, c = i & 7;
        const size_t g = ((size_t)(bi * cT + t0 + r) * cH + hh) * cDK + c * 8;
        *reinterpret_cast<uint4*>(smb + r * ROW2 + c * 16) =
            *reinterpret_cast<const uint4*>(qh + g);
    }
    __syncthreads();

    uint32_t qfh[4][4];
    #pragma unroll
    for (int kb = 0; kb < 4; kb++) {
        const int row = wid * 16 + (lane & 15);
        const int col = kb * 16 + ((lane >> 4) << 3);
        ldsm4(qfh[kb][0], qfh[kb][1], qfh[kb][2], qfh[kb][3],
              sb + (uint32_t)(row * ROW2 + col * 2));
    }
    __syncthreads();   // stage area free for K/V

    const int lr = tid >> 3, lc8 = (tid & 7);
    auto load_kv = [&](int s0, int stage) {
        const uint32_t st = sb + stage * STG2;
        #pragma unroll
        for (int it = 0; it < 2; it++) {
            const int r = lr + it * 32;
            const uint32_t so = (uint32_t)(r * ROW2 + lc8 * 16);
            const size_t g = ((size_t)(bi * cS + s0 + r) * cH + hh) * cDK + lc8 * 8;
            cp16(st + R_KH + so, kh + g);
            cp16(st + R_VH + so, vh + g);
        }
        CP_COMMIT();
    };

    float oacc[8][4] = {};
    float mrow0 = -INFINITY, mrow1 = -INFINITY;
    float lrow0 = 0.0f, lrow1 = 0.0f;

    const int quad = lane >> 3, id8 = lane & 7;
    constexpr uint32_t ONES2 = 0x3C003C00u;   // half2(1.0, 1.0)
    constexpr int NT = cS / 64;

    load_kv(0, 0);
    load_kv(64, 1);
    load_kv(128, 2);

    for (int ch = 0; ch < NT; ch++) {
        CP_WAIT(2);
        __syncthreads();
        const uint32_t st = sb + (ch & 3) * STG2;

        // ---- S = Qh*Kh (1-term)
        float sacc[8][4] = {};
        #pragma unroll
        for (int kb = 0; kb < 4; kb++) {
            #pragma unroll
            for (int np = 0; np < 4; np++) {
                const int nrow = np * 16 + (lane & 7) + ((lane >> 4) << 3);
                const int col = kb * 16 + (((lane >> 3) & 1) << 3);
                uint32_t h0, h1, h2, h3;
                ldsm4(h0, h1, h2, h3, st + (uint32_t)(R_KH + nrow * ROW2 + col * 2));
                mma_f16(sacc[2 * np], qfh[kb][0], qfh[kb][1], qfh[kb][2], qfh[kb][3], h0, h1);
                mma_f16(sacc[2 * np + 1], qfh[kb][0], qfh[kb][1], qfh[kb][2], qfh[kb][3], h2, h3);
            }
        }

        // prefetch tile ch+3 now so cp.async overlaps softmax + PV
        if (ch + 3 < NT) load_kv((ch + 3) * 64, (ch + 3) & 3);
        else             CP_COMMIT();

        // ---- max reduction (fp32)
        float mx0 = -INFINITY, mx1 = -INFINITY;
        #pragma unroll
        for (int n = 0; n < 8; n++) {
            mx0 = fmaxf(mx0, fmaxf(sacc[n][0], sacc[n][1]));
            mx1 = fmaxf(mx1, fmaxf(sacc[n][2], sacc[n][3]));
        }
        mx0 = fmaxf(mx0, __shfl_xor_sync(0xffffffffu, mx0, 1));
        mx0 = fmaxf(mx0, __shfl_xor_sync(0xffffffffu, mx0, 2));
        mx1 = fmaxf(mx1, __shfl_xor_sync(0xffffffffu, mx1, 1));
        mx1 = fmaxf(mx1, __shfl_xor_sync(0xffffffffu, mx1, 2));
        const float mn0 = fmaxf(mrow0, mx0);
        const float mn1 = fmaxf(mrow1, mx1);
        const float corr0 = ex2(mrow0 - mn0);
        const float corr1 = ex2(mrow1 - mn1);
        mrow0 = mn0;  mrow1 = mn1;

        // ---- P = ex2(S - m) in packed fp16; row sums via ones-MMA
        uint32_t pah[4][4];
        float sumacc[4] = {0.f, 0.f, 0.f, 0.f};
        #pragma unroll
        for (int kb = 0; kb < 4; kb++) {
            pah[kb][0] = ex2h2(packh2(sacc[2 * kb][0] - mn0, sacc[2 * kb][1] - mn0));
            pah[kb][1] = ex2h2(packh2(sacc[2 * kb][2] - mn1, sacc[2 * kb][3] - mn1));
            pah[kb][2] = ex2h2(packh2(sacc[2 * kb + 1][0] - mn0, sacc[2 * kb + 1][1] - mn0));
            pah[kb][3] = ex2h2(packh2(sacc[2 * kb + 1][2] - mn1, sacc[2 * kb + 1][3] - mn1));
            mma_f16(sumacc, pah[kb][0], pah[kb][1], pah[kb][2], pah[kb][3],
                    ONES2, ONES2);
        }
        lrow0 = lrow0 * corr0 + sumacc[0];
        lrow1 = lrow1 * corr1 + sumacc[2];

        #pragma unroll
        for (int n = 0; n < 8; n++) {
            oacc[n][0] *= corr0; oacc[n][1] *= corr0;
            oacc[n][2] *= corr1; oacc[n][3] *= corr1;
        }

        // ---- O += Ph*Vh (V natural, trans-ldsm B-fragments)
        #pragma unroll
        for (int kb = 0; kb < 4; kb++) {
            #pragma unroll
            for (int np = 0; np < 4; np++) {
                const uint32_t av = (uint32_t)(
                    (kb * 16 + (quad & 1) * 8 + id8) * ROW2 +
                    (np * 16 + (quad >> 1) * 8) * 2);
                uint32_t h0, h1, h2, h3;
                ldsm4t(h0, h1, h2, h3, st + R_VH + av);
                mma_f16(oacc[2 * np], pah[kb][0], pah[kb][1], pah[kb][2], pah[kb][3], h0, h1);
                mma_f16(oacc[2 * np + 1], pah[kb][0], pah[kb][1], pah[kb][2], pah[kb][3], h2, h3);
            }
        }
    }

    // ---- Normalize + write O as fp16 hi/lo (base addresses hoisted)
    const float inv0 = 1.0f / lrow0;
    const float inv1 = 1.0f / lrow1;
    const int row0 = t0 + wid * 16 + (lane >> 2);
    const size_t base0 = ((size_t)(bi * cT + row0) * cH + hh) * cDK + (lane & 3) * 2;
    const size_t base1 = ((size_t)(bi * cT + row0 + 8) * cH + hh) * cDK + (lane & 3) * 2;
    #pragma unroll
    for (int n = 0; n < 8; n++) {
        const int dk = n * 8;
        uint32_t hp, lp;
        hilo2h(oacc[n][0] * inv0, oacc[n][1] * inv0, hp, lp);
        *reinterpret_cast<uint32_t*>(oh + base0 + dk) = hp;
        *reinterpret_cast<uint32_t*>(ol + base0 + dk) = lp;
        hilo2h(oacc[n][2] * inv1, oacc[n][3] * inv1, hp, lp);
        *reinterpret_cast<uint32_t*>(oh + base1 + dk) = hp;
        *reinterpret_cast<uint32_t*>(ol + base1 + dk) = lp;
    }
}

// ---------------------------------------------------------------------------
extern "C" void kernel_launch(void* const* d_in, const int* in_sizes, int n_in,
                              void* d_out, int out_size)
{
    const float* query = (const float*)d_in[0];
    const float* value = (const float*)d_in[1];
    const float* key   = (const float*)d_in[2];
    const float* Wq    = (const float*)d_in[3];
    const float* bq    = (const float*)d_in[4];
    const float* Wk    = (const float*)d_in[5];
    const float* bk    = (const float*)d_in[6];
    const float* Wv    = (const float*)d_in[7];
    const float* bv    = (const float*)d_in[8];
    const float* Wo    = (const float*)d_in[9];
    const float* bo    = (const float*)d_in[10];
    float* out = (float*)d_out;

    f16 *xh, *xl, *yh, *wh, *wl;
    cudaGetSymbolAddress((void**)&xh, g_xh);
    cudaGetSymbolAddress((void**)&xl, g_xl);
    cudaGetSymbolAddress((void**)&yh, g_yh);
    cudaGetSymbolAddress((void**)&wh, g_wth);
    cudaGetSymbolAddress((void**)&wl, g_wtl);

    cudaFuncSetAttribute(gemm_mma<true>,
                         cudaFuncAttributeMaxDynamicSharedMemorySize, GEMM_SMEM);
    cudaFuncSetAttribute(gemm_mma<false>,
                         cudaFuncAttributeMaxDynamicSharedMemorySize, GEMM_SMEM);

    const int XB = (int)(XSZ / 4 / 256);

    xconv3<<<dim3(XB, 1, 3), 256>>>(query, key, value, xh, xl);
    wconv<<<dim3(32, 32, 4), dim3(32, 8)>>>(Wq, Wk, Wv, Wo, wh, wl);

    // Q/K/V projections, all 2-term (Xh*Wh + Xl*Wh), fp16-hi outputs only;
    // Q scaled by 1/sqrt(DK)*log2(e)
    const float qscale = 0.125f * 1.44269504088896340736f;
    gemm_mma<true><<<dim3(cHD / 128, cMT / 128, 3), 256, GEMM_SMEM>>>(
        xh, xl, wh, wl, bq, bk, bv, nullptr, yh, qscale, 0b111);

    // 1-term fp16 attention; out -> x slot 0 hi/lo
    attn_mma<<<dim3(cT / 128, cH, cB), 256>>>(
        yh, yh + XSZ, yh + 2 * XSZ, xh, xl);

    // O projection (fp32 out, 2-term: Xh*Wh + Xl*Wh — W-lo below the noise
    // floor of the attention output flowing through it)
    gemm_mma<false><<<dim3(cD / 128, cMT / 128, 1), 256, GEMM_SMEM>>>(
        xh, xl, wh + 3 * WSZ, wl + 3 * WSZ, bo, bo, bo, out, nullptr,
        1.0f, 1);
}